// round 16
// baseline (speedup 1.0000x reference)
#include <cuda_runtime.h>
#include <cuda_fp16.h>
#include <cstdint>

#define DEVI __device__ __forceinline__

// ---- problem constants ----
#define NB 4
#define NL 2048
#define ND 512
#define NH 8
#define HD 64
#define NBH (NB*NH)

// ---- scratch ----
static __device__ __half g_qh[(size_t)NBH * NL * HD];
static __device__ __half g_kh[(size_t)NBH * NL * HD];
static __device__ __half g_vh[(size_t)NBH * NL * HD];
static __device__ __half g_xh[3][(size_t)NB * NL * ND];     // fp16 x_q, x_k, x_v
static __device__ __half g_wh[4][(size_t)ND * ND];          // fp16 Wq, Wk, Wv, Wo
static __device__ __half g_mb[(size_t)NB * NL * NL];        // fp16 mask bias (0 / -60000)
static __device__ __half g_ph[(size_t)NBH * NL * NL];       // unnormalized exp (P~) fp16
static __device__ __half g_ctxh[(size_t)NB * NL * ND];
static __device__ float  g_final[(size_t)NB * NL * ND];
static __device__ float  g_attn[(size_t)NBH * NL * NL];     // fallback if attn not in d_out

// ---- PTX helpers ----
DEVI void mma_f16(float c[4], const uint32_t a[4], const uint32_t b[2]) {
    asm volatile(
        "mma.sync.aligned.m16n8k16.row.col.f32.f16.f16.f32 "
        "{%0,%1,%2,%3},{%4,%5,%6,%7},{%8,%9},{%0,%1,%2,%3};"
        : "+f"(c[0]), "+f"(c[1]), "+f"(c[2]), "+f"(c[3])
        : "r"(a[0]), "r"(a[1]), "r"(a[2]), "r"(a[3]), "r"(b[0]), "r"(b[1]));
}
DEVI void ldsm_x4(uint32_t r[4], uint32_t addr) {
    asm volatile("ldmatrix.sync.aligned.m8n8.x4.shared.b16 {%0,%1,%2,%3}, [%4];"
        : "=r"(r[0]), "=r"(r[1]), "=r"(r[2]), "=r"(r[3]) : "r"(addr));
}
DEVI void ldsm_x4_t(uint32_t r[4], uint32_t addr) {
    asm volatile("ldmatrix.sync.aligned.m8n8.x4.trans.shared.b16 {%0,%1,%2,%3}, [%4];"
        : "=r"(r[0]), "=r"(r[1]), "=r"(r[2]), "=r"(r[3]) : "r"(addr));
}
DEVI void cpa16(void* s, const void* g) {
    uint32_t sa = (uint32_t)__cvta_generic_to_shared(s);
    asm volatile("cp.async.cg.shared.global [%0], [%1], 16;" :: "r"(sa), "l"(g));
}
DEVI void cp_commit() { asm volatile("cp.async.commit_group;"); }
template <int N> DEVI void cp_wait() { asm volatile("cp.async.wait_group %0;" :: "n"(N)); }
DEVI uint32_t packh2(float a, float b) {
    __half2 h = __floats2half2_rn(a, b);
    return *reinterpret_cast<uint32_t*>(&h);
}

// ============================================================================
// conversion kernels (one-time per launch, streaming; fused launches)
// ============================================================================
__global__ void cvt_f16_x3(const float4* __restrict__ a, const float4* __restrict__ b,
                           const float4* __restrict__ c, uint2* __restrict__ out) {
    int i = blockIdx.x * blockDim.x + threadIdx.x;          // 3 * (1<<20) total
    int which = i >> 20, off = i & ((1 << 20) - 1);
    const float4* src = (which == 0) ? a : (which == 1) ? b : c;
    float4 v = src[off];
    out[i] = make_uint2(packh2(v.x, v.y), packh2(v.z, v.w));
}
__global__ void cvt_f16_w4(const float4* __restrict__ a, const float4* __restrict__ b,
                           const float4* __restrict__ c, const float4* __restrict__ d,
                           uint2* __restrict__ out) {
    int i = blockIdx.x * blockDim.x + threadIdx.x;          // 4 * (1<<16) total
    int which = i >> 16, off = i & ((1 << 16) - 1);
    const float4* src = (which == 0) ? a : (which == 1) ? b : (which == 2) ? c : d;
    float4 v = src[off];
    out[i] = make_uint2(packh2(v.x, v.y), packh2(v.z, v.w));
}
__global__ void cvt_maskbias(const int4* __restrict__ in, uint2* __restrict__ out, int n4) {
    int i = blockIdx.x * blockDim.x + threadIdx.x;
    if (i < n4) {
        int4 m = in[i];
        out[i] = make_uint2(
            packh2(m.x ? -60000.f : 0.f, m.y ? -60000.f : 0.f),
            packh2(m.z ? -60000.f : 0.f, m.w ? -60000.f : 0.f));
    }
}

// ============================================================================
// fp16 TN GEMM (unchanged): out[m,n] = sum_k A[m,k]*W[n,k] + bias[n]
// ============================================================================
template <int PERM, typename OutT>
__global__ __launch_bounds__(256, 2) void gemm16(
    const __half* __restrict__ A, const __half* __restrict__ W,
    const float* __restrict__ bias, OutT* __restrict__ out)
{
    extern __shared__ __align__(16) __half smh[];
    __half* As = smh;             // [2][128*40]
    __half* Bs = smh + 2 * 5120;  // [2][128*40]
    const int tid = threadIdx.x, lane = tid & 31, wid = tid >> 5;
    const int wm = wid & 3, wn = wid >> 2;
    const int m0 = blockIdx.x * 128, n0 = blockIdx.y * 128;
    const uint32_t shb = (uint32_t)__cvta_generic_to_shared(smh);

    float acc[2][8][4];
#pragma unroll
    for (int i = 0; i < 2; i++)
#pragma unroll
        for (int j = 0; j < 8; j++)
#pragma unroll
            for (int e = 0; e < 4; e++) acc[i][j][e] = 0.f;

    const int lr = tid >> 1, lc = (tid & 1) * 16;
    auto load_tile = [&](int buf, int kt) {
        const __half* ag = A + (size_t)(m0 + lr) * 512 + kt * 32 + lc;
        const __half* bg = W + (size_t)(n0 + lr) * 512 + kt * 32 + lc;
        __half* as = &As[buf * 5120 + lr * 40 + lc];
        __half* bs = &Bs[buf * 5120 + lr * 40 + lc];
        cpa16(as,     ag);
        cpa16(as + 8, ag + 8);
        cpa16(bs,     bg);
        cpa16(bs + 8, bg + 8);
        cp_commit();
    };
    const uint32_t a_loff =
        ((uint32_t)((lane & 7) + ((lane >> 3) & 1) * 8) * 40 + (lane >> 4) * 8) * 2;
    const uint32_t b_loff =
        ((uint32_t)((lane & 7) + ((lane >> 4) << 3)) * 40 + ((lane >> 3) & 1) * 8) * 2;

    load_tile(0, 0);
    for (int kt = 0; kt < 16; kt++) {
        if (kt < 15) { load_tile((kt + 1) & 1, kt + 1); cp_wait<1>(); }
        else         { cp_wait<0>(); }
        __syncthreads();
        const uint32_t abase = shb + (uint32_t)((kt & 1) * 5120) * 2 + a_loff;
        const uint32_t bbase = shb + (uint32_t)(2 * 5120 + (kt & 1) * 5120) * 2 + b_loff;
#pragma unroll
        for (int ks = 0; ks < 2; ks++) {
            uint32_t af[2][4], bf[4][4];
#pragma unroll
            for (int mi = 0; mi < 2; mi++)
                ldsm_x4(af[mi], abase + (uint32_t)((wm * 32 + mi * 16) * 40 + ks * 16) * 2);
#pragma unroll
            for (int jn = 0; jn < 4; jn++)
                ldsm_x4(bf[jn], bbase + (uint32_t)((wn * 64 + jn * 16) * 40 + ks * 16) * 2);
#pragma unroll
            for (int mi = 0; mi < 2; mi++)
#pragma unroll
                for (int jn = 0; jn < 4; jn++) {
                    mma_f16(acc[mi][2 * jn],     af[mi], &bf[jn][0]);
                    mma_f16(acc[mi][2 * jn + 1], af[mi], &bf[jn][2]);
                }
        }
        __syncthreads();
    }

#pragma unroll
    for (int i = 0; i < 2; i++)
#pragma unroll
        for (int j = 0; j < 8; j++)
#pragma unroll
            for (int e = 0; e < 4; e++) {
                int row = m0 + wm * 32 + i * 16 + (lane >> 2) + ((e >> 1) * 8);
                int col = n0 + wn * 64 + j * 8 + ((lane & 3) * 2) + (e & 1);
                float v = acc[i][j][e] + __ldg(&bias[col]);
                if (PERM) {
                    int bb = row >> 11, l = row & (NL - 1);
                    out[(((size_t)(bb * NH + (col >> 6))) * NL + l) * HD + (col & 63)] = (OutT)v;
                } else {
                    out[(size_t)row * ND + col] = (OutT)v;
                }
            }
}

// ============================================================================
// Fused attention, 128 q-rows/CTA, NO QK recompute:
//   Sweep 1: QK^T -> P~ = exp(s/8+bias) (fp16, STG to g_ph) + fp32 row sums
//   Sweep 2: LDG P~ back -> attn = P~*il (write once) + P.V with raw P~;
//            normalization folded into O epilogue (O = oacc * il).
// smem: Qs[128][72] + Ks[2][64][72] + Vs[2][64][72] + invl/lpart  = 56,320 B
// ============================================================================
__global__ __launch_bounds__(256, 2) void attn_fused(
    const __half* __restrict__ Q, const __half* __restrict__ K,
    const __half* __restrict__ V, const __half* __restrict__ mbias,
    __half* __restrict__ ph, float* __restrict__ attn, __half* __restrict__ ctx)
{
    extern __shared__ __align__(16) __half sh[];
    __half* Qs = sh;                         // 128*72
    __half* Ks = sh + 9216;                  // 2 * 64*72
    __half* Vs = sh + 18432;                 // 2 * 64*72
    float* invl  = (float*)(sh + 27648);     // 128
    float* lpart = invl + 128;               // 128

    const int tid = threadIdx.x, lane = tid & 31, wid = tid >> 5;
    const int wq = wid;                      // 16 q-rows per warp
    const int bh = blockIdx.y, b = bh >> 3, h = bh & 7;
    const int q0 = blockIdx.x * 128;

    const __half* Qg = Q + ((size_t)bh * NL + q0) * HD;
    const __half* Kg = K + (size_t)bh * NL * HD;
    const __half* Vg = V + (size_t)bh * NL * HD;
    const __half* mbb = mbias + (size_t)b * NL * NL;

    const uint32_t shb = (uint32_t)__cvta_generic_to_shared(sh);
    const uint32_t k_loff =
        ((uint32_t)(((lane >> 4) << 3) + (lane & 7)) * 72 + (((lane >> 3) & 1) << 3)) * 2;
    const uint32_t v_loff =
        ((uint32_t)((((lane >> 3) & 1) << 3) + (lane & 7)) * 72 + ((lane >> 4) << 3)) * 2;

    const int ldr = tid >> 3, ldc = (tid & 7) * 8;

    auto loadQ = [&]() {
#pragma unroll
        for (int i = 0; i < 4; i++) {
            int r = ldr + 32 * i;
            cpa16(&Qs[r * 72 + ldc], Qg + (size_t)r * HD + ldc);
        }
    };
    auto loadK = [&](int buf, int ch) {
#pragma unroll
        for (int i = 0; i < 2; i++) {
            int r = ldr + 32 * i;
            cpa16(&Ks[buf * 4608 + r * 72 + ldc], Kg + (size_t)(ch * 64 + r) * HD + ldc);
        }
    };
    auto loadV = [&](int buf, int ch) {
#pragma unroll
        for (int i = 0; i < 2; i++) {
            int r = ldr + 32 * i;
            cpa16(&Vs[buf * 4608 + r * 72 + ldc], Vg + (size_t)(ch * 64 + r) * HD + ldc);
        }
    };

    const int rq  = wq * 16 + (lane >> 2);     // local q row (and +8)
    const int r0g = q0 + rq;                   // global q row
    const int kc  = (lane & 3) * 2;
    const size_t prow0 = ((size_t)bh * NL + r0g) * NL;   // P~ row base (this lane)
    const size_t prow8 = prow0 + (size_t)8 * NL;

    uint32_t qf[4][4];
    float lsum0 = 0.f, lsum1 = 0.f;

    // ---------------- sweep 1: QK -> P~ store + row sums ----------------
    loadQ(); loadK(0, 0); cp_commit();
    for (int ch = 0; ch < 32; ch++) {
        if (ch < 31) { loadK((ch + 1) & 1, ch + 1); cp_commit(); cp_wait<1>(); }
        else         { cp_wait<0>(); }
        __syncthreads();
        if (ch == 0) {
#pragma unroll
            for (int s = 0; s < 4; s++) {
                int k0 = s * 16 + kc;
                qf[s][0] = *(const uint32_t*)&Qs[rq * 72 + k0];
                qf[s][1] = *(const uint32_t*)&Qs[(rq + 8) * 72 + k0];
                qf[s][2] = *(const uint32_t*)&Qs[rq * 72 + k0 + 8];
                qf[s][3] = *(const uint32_t*)&Qs[(rq + 8) * 72 + k0 + 8];
            }
        }
        const uint32_t ksb = shb + (uint32_t)(9216 + (ch & 1) * 4608) * 2 + k_loff;

        float acc[8][4];
#pragma unroll
        for (int j = 0; j < 8; j++)
#pragma unroll
            for (int e = 0; e < 4; e++) acc[j][e] = 0.f;
#pragma unroll
        for (int jp = 0; jp < 4; jp++)
#pragma unroll
            for (int s = 0; s < 4; s++) {
                uint32_t r[4];
                ldsm_x4(r, ksb + (uint32_t)(jp * 16 * 72 + s * 16) * 2);
                mma_f16(acc[2 * jp],     qf[s], &r[0]);
                mma_f16(acc[2 * jp + 1], qf[s], &r[2]);
            }
#pragma unroll
        for (int j = 0; j < 8; j++) {
            int colg = ch * 64 + j * 8 + kc;
            float2 f0 = __half22float2(*(const __half2*)&mbb[prow0 - (size_t)bh * NL * NL
                                       - (size_t)(b * 0) + 0 ? 0 : 0]);  // (placeholder removed below)
            (void)f0;
            float2 m0 = __half22float2(*(const __half2*)&mbb[(size_t)r0g * NL + colg]);
            float2 m1 = __half22float2(*(const __half2*)&mbb[(size_t)(r0g + 8) * NL + colg]);
            float e0 = __expf(fmaf(acc[j][0], 0.125f, m0.x));
            float e1 = __expf(fmaf(acc[j][1], 0.125f, m0.y));
            float e2 = __expf(fmaf(acc[j][2], 0.125f, m1.x));
            float e3 = __expf(fmaf(acc[j][3], 0.125f, m1.y));
            lsum0 += e0 + e1;
            lsum1 += e2 + e3;
            *(uint32_t*)&ph[prow0 + colg] = packh2(e0, e1);
            *(uint32_t*)&ph[prow8 + colg] = packh2(e2, e3);
        }
        __syncthreads();
    }
    lsum0 += __shfl_xor_sync(0xffffffffu, lsum0, 1);
    lsum0 += __shfl_xor_sync(0xffffffffu, lsum0, 2);
    lsum1 += __shfl_xor_sync(0xffffffffu, lsum1, 1);
    lsum1 += __shfl_xor_sync(0xffffffffu, lsum1, 2);
    if ((lane & 3) == 0) {
        lpart[rq]     = lsum0;
        lpart[rq + 8] = lsum1;
    }
    __syncthreads();
    if (tid < 128) invl[tid] = 1.0f / lpart[tid];
    __syncthreads();

    const float il0 = invl[rq], il1 = invl[rq + 8];

    float oacc[8][4];
#pragma unroll
    for (int j = 0; j < 8; j++)
#pragma unroll
        for (int e = 0; e < 4; e++) oacc[j][e] = 0.f;

    // ---------------- sweep 2: P~ readback -> attn write + P.V ----------------
    loadV(0, 0); cp_commit();
    for (int ch = 0; ch < 32; ch++) {
        // issue P~ loads early (independent of smem) to hide DRAM latency
        uint32_t pld0[8], pld1[8];
#pragma unroll
        for (int j = 0; j < 8; j++) {
            size_t pc = (size_t)(ch * 64 + j * 8 + kc);
            pld0[j] = *(const uint32_t*)&ph[prow0 + pc];
            pld1[j] = *(const uint32_t*)&ph[prow8 + pc];
        }
        if (ch < 31) { loadV((ch + 1) & 1, ch + 1); cp_commit(); cp_wait<1>(); }
        else         { cp_wait<0>(); }
        __syncthreads();
        const uint32_t vsb = shb + (uint32_t)(18432 + (ch & 1) * 4608) * 2 + v_loff;

        // attn = P~ * il  (single write of the attention output)
#pragma unroll
        for (int j = 0; j < 8; j++) {
            int colg = ch * 64 + j * 8 + kc;
            float2 a0 = __half22float2(*(const __half2*)&pld0[j]);
            float2 a1 = __half22float2(*(const __half2*)&pld1[j]);
            a0.x *= il0; a0.y *= il0;
            a1.x *= il1; a1.y *= il1;
            *(float2*)&attn[prow0 + colg] = a0;
            *(float2*)&attn[prow8 + colg] = a1;
        }
        // P.V with raw (unnormalized) P~; normalization folded into epilogue
#pragma unroll
        for (int s2 = 0; s2 < 4; s2++) {
            uint32_t pa[4] = { pld0[2 * s2], pld1[2 * s2], pld0[2 * s2 + 1], pld1[2 * s2 + 1] };
#pragma unroll
            for (int jnp = 0; jnp < 4; jnp++) {
                uint32_t r[4];
                ldsm_x4_t(r, vsb + (uint32_t)(s2 * 16 * 72 + jnp * 16) * 2);
                mma_f16(oacc[2 * jnp],     pa, &r[0]);
                mma_f16(oacc[2 * jnp + 1], pa, &r[2]);
            }
        }
        __syncthreads();
    }

    // ---------------- ctx store (fp16), O = oacc * il ----------
    float* osum = (float*)Ks;   // 128 x 72 f32 = 36,864 B = Ks+Vs regions
#pragma unroll
    for (int jn = 0; jn < 8; jn++)
#pragma unroll
        for (int e = 0; e < 4; e++) {
            int row = wq * 16 + (lane >> 2) + (e >> 1) * 8;
            int col = jn * 8 + kc + (e & 1);
            osum[row * 72 + col] = oacc[jn][e] * ((e >> 1) ? il1 : il0);
        }
    __syncthreads();
    for (int i = tid; i < 128 * 16; i += 256) {
        int row = i >> 4, c4 = (i & 15) * 4;
        float4 v = *(const float4*)&osum[row * 72 + c4];
        uint2 o = make_uint2(packh2(v.x, v.y), packh2(v.z, v.w));
        *(uint2*)&ctx[((size_t)b * NL + q0 + row) * ND + h * HD + c4] = o;
    }
}

// ============================================================================
// launch
// ============================================================================
extern "C" void kernel_launch(void* const* d_in, const int* in_sizes, int n_in,
                              void* d_out, int out_size) {
    (void)in_sizes; (void)n_in;
    const float* xs[3] = { (const float*)d_in[0], (const float*)d_in[1], (const float*)d_in[2] };
    const int*   msk = (const int*)d_in[3];
    const float* Ws[4] = { (const float*)d_in[4], (const float*)d_in[6],
                           (const float*)d_in[8], (const float*)d_in[10] };
    const float* bq = (const float*)d_in[5];
    const float* bk = (const float*)d_in[7];
    const float* bv = (const float*)d_in[9];
    const float* bo = (const float*)d_in[11];

    const long long FINAL_N = (long long)NB * NL * ND;
    const long long ATTN_N  = (long long)NBH * NL * NL;

    float* outp = (float*)d_out;
    float *finalp, *attnp;
    if ((long long)out_size >= FINAL_N + ATTN_N) { finalp = outp; attnp = outp + FINAL_N; }
    else if ((long long)out_size == ATTN_N)      { attnp = outp;  finalp = g_final; }
    else                                         { finalp = outp; attnp = g_attn; }

    const int SM_G16  = 4 * 5120 * 2;                       // 40,960 B
    const int SM_ATTN = 27648 * 2 + 256 * 4;                // 56,320 B

    cudaFuncSetAttribute(gemm16<1, __half>, cudaFuncAttributeMaxDynamicSharedMemorySize, SM_G16);
    cudaFuncSetAttribute(gemm16<0, float>,  cudaFuncAttributeMaxDynamicSharedMemorySize, SM_G16);
    cudaFuncSetAttribute(attn_fused, cudaFuncAttributeMaxDynamicSharedMemorySize, SM_ATTN);

    __half* qg;  cudaGetSymbolAddress((void**)&qg, g_qh);
    __half* kg;  cudaGetSymbolAddress((void**)&kg, g_kh);
    __half* vg;  cudaGetSymbolAddress((void**)&vg, g_vh);
    __half* xh;  cudaGetSymbolAddress((void**)&xh, g_xh);
    __half* wh;  cudaGetSymbolAddress((void**)&wh, g_wh);
    __half* mb;  cudaGetSymbolAddress((void**)&mb, g_mb);
    __half* phg; cudaGetSymbolAddress((void**)&phg, g_ph);
    __half* cg;  cudaGetSymbolAddress((void**)&cg, g_ctxh);

    const size_t XN = (size_t)NB * NL * ND;      // 4,194,304  (XN/4 = 1<<20)
    const size_t WN = (size_t)ND * ND;           //   262,144  (WN/4 = 1<<16)
    const size_t MN = (size_t)NB * NL * NL;      // 16,777,216

    // conversions (fused launches)
    cvt_f16_x3<<<(int)(3 * (XN / 4) / 256), 256>>>(
        (const float4*)xs[0], (const float4*)xs[1], (const float4*)xs[2], (uint2*)xh);
    cvt_f16_w4<<<(int)(4 * (WN / 4) / 256), 256>>>(
        (const float4*)Ws[0], (const float4*)Ws[1], (const float4*)Ws[2], (const float4*)Ws[3],
        (uint2*)wh);
    cvt_maskbias<<<(int)(MN / 4 / 256), 256>>>((const int4*)msk, (uint2*)mb, (int)(MN / 4));

    // projections (fp16)
    dim3 gp(64, 4);
    gemm16<1, __half><<<gp, 256, SM_G16>>>(xh + 0 * XN, wh + 0 * WN, bq, qg);
    gemm16<1, __half><<<gp, 256, SM_G16>>>(xh + 1 * XN, wh + 1 * WN, bk, kg);
    gemm16<1, __half><<<gp, 256, SM_G16>>>(xh + 2 * XN, wh + 2 * WN, bv, vg);

    // fused attention: 128 q-rows per CTA, P~ roundtrip instead of QK recompute
    attn_fused<<<dim3(NL / 128, NBH), 256, SM_ATTN>>>(qg, kg, vg, mb, phg, attnp, cg);

    // output projection (fp16 inputs, fp32 out)
    gemm16<0, float><<<gp, 256, SM_G16>>>(cg, wh + 3 * WN, bo, finalp);
}

// round 17
// speedup vs baseline: 1.1248x; 1.1248x over previous
#include <cuda_runtime.h>
#include <cuda_fp16.h>
#include <cstdint>

#define DEVI __device__ __forceinline__

// ---- problem constants ----
#define NB 4
#define NL 2048
#define ND 512
#define NH 8
#define HD 64
#define NBH (NB*NH)

// ---- scratch ----
static __device__ __half g_qh[(size_t)NBH * NL * HD];
static __device__ __half g_kh[(size_t)NBH * NL * HD];
static __device__ __half g_vh[(size_t)NBH * NL * HD];
static __device__ __half g_xh[3][(size_t)NB * NL * ND];     // fp16 x_q, x_k, x_v
static __device__ __half g_wh[4][(size_t)ND * ND];          // fp16 Wq, Wk, Wv, Wo
static __device__ __half g_mb[(size_t)NB * NL * NL];        // fp16 mask bias (0 / -60000)
static __device__ __half g_ctxh[(size_t)NB * NL * ND];
static __device__ float  g_final[(size_t)NB * NL * ND];
static __device__ float  g_attn[(size_t)NBH * NL * NL];     // fallback if attn not in d_out

// ---- PTX helpers ----
DEVI void mma_f16(float c[4], const uint32_t a[4], const uint32_t b[2]) {
    asm volatile(
        "mma.sync.aligned.m16n8k16.row.col.f32.f16.f16.f32 "
        "{%0,%1,%2,%3},{%4,%5,%6,%7},{%8,%9},{%0,%1,%2,%3};"
        : "+f"(c[0]), "+f"(c[1]), "+f"(c[2]), "+f"(c[3])
        : "r"(a[0]), "r"(a[1]), "r"(a[2]), "r"(a[3]), "r"(b[0]), "r"(b[1]));
}
DEVI void ldsm_x4(uint32_t r[4], uint32_t addr) {
    asm volatile("ldmatrix.sync.aligned.m8n8.x4.shared.b16 {%0,%1,%2,%3}, [%4];"
        : "=r"(r[0]), "=r"(r[1]), "=r"(r[2]), "=r"(r[3]) : "r"(addr));
}
DEVI void ldsm_x4_t(uint32_t r[4], uint32_t addr) {
    asm volatile("ldmatrix.sync.aligned.m8n8.x4.trans.shared.b16 {%0,%1,%2,%3}, [%4];"
        : "=r"(r[0]), "=r"(r[1]), "=r"(r[2]), "=r"(r[3]) : "r"(addr));
}
DEVI void cpa16(void* s, const void* g) {
    uint32_t sa = (uint32_t)__cvta_generic_to_shared(s);
    asm volatile("cp.async.cg.shared.global [%0], [%1], 16;" :: "r"(sa), "l"(g));
}
DEVI void cp_commit() { asm volatile("cp.async.commit_group;"); }
template <int N> DEVI void cp_wait() { asm volatile("cp.async.wait_group %0;" :: "n"(N)); }
DEVI uint32_t packh2(float a, float b) {
    __half2 h = __floats2half2_rn(a, b);
    return *reinterpret_cast<uint32_t*>(&h);
}

// ============================================================================
// conversion kernels (one-time per launch, streaming; fused launches)
// ============================================================================
__global__ void cvt_f16_x3(const float4* __restrict__ a, const float4* __restrict__ b,
                           const float4* __restrict__ c, uint2* __restrict__ out) {
    int i = blockIdx.x * blockDim.x + threadIdx.x;          // 3 * (1<<20) total
    int which = i >> 20, off = i & ((1 << 20) - 1);
    const float4* src = (which == 0) ? a : (which == 1) ? b : c;
    float4 v = src[off];
    out[i] = make_uint2(packh2(v.x, v.y), packh2(v.z, v.w));
}
__global__ void cvt_f16_w4(const float4* __restrict__ a, const float4* __restrict__ b,
                           const float4* __restrict__ c, const float4* __restrict__ d,
                           uint2* __restrict__ out) {
    int i = blockIdx.x * blockDim.x + threadIdx.x;          // 4 * (1<<16) total
    int which = i >> 16, off = i & ((1 << 16) - 1);
    const float4* src = (which == 0) ? a : (which == 1) ? b : (which == 2) ? c : d;
    float4 v = src[off];
    out[i] = make_uint2(packh2(v.x, v.y), packh2(v.z, v.w));
}
__global__ void cvt_maskbias(const int4* __restrict__ in, uint2* __restrict__ out, int n4) {
    int i = blockIdx.x * blockDim.x + threadIdx.x;
    if (i < n4) {
        int4 m = in[i];
        out[i] = make_uint2(
            packh2(m.x ? -60000.f : 0.f, m.y ? -60000.f : 0.f),
            packh2(m.z ? -60000.f : 0.f, m.w ? -60000.f : 0.f));
    }
}

// ============================================================================
// fp16 TN GEMM body, 4-stage cp.async pipeline, single sync per k-iter.
//   out[m,n] = sum_k A[m,k]*W[n,k] + bias[n].  M=8192, N=512, K=512.
//   PERM=1 (half out): head-split [BH, L, 64]; PERM=0 (float out): [M, 512].
// BM=BN=128, BK=32, 256 thr (8 warps, warp 32x64), ldmatrix + m16n8k16.
// smem: As/Bs [4][128][40]h = 81,920 B total.
// ============================================================================
template <int PERM, typename OutT>
DEVI void gemm16_body(const __half* __restrict__ A, const __half* __restrict__ W,
                      const float* __restrict__ bias, OutT* __restrict__ out,
                      int m0, int n0)
{
    extern __shared__ __align__(16) __half smh[];
    __half* As = smh;               // [4][128*40]
    __half* Bs = smh + 4 * 5120;    // [4][128*40]
    const int tid = threadIdx.x, lane = tid & 31, wid = tid >> 5;
    const int wm = wid & 3, wn = wid >> 2;
    const uint32_t shb = (uint32_t)__cvta_generic_to_shared(smh);

    float acc[2][8][4];
#pragma unroll
    for (int i = 0; i < 2; i++)
#pragma unroll
        for (int j = 0; j < 8; j++)
#pragma unroll
            for (int e = 0; e < 4; e++) acc[i][j][e] = 0.f;

    const int lr = tid >> 1, lc = (tid & 1) * 16;
    auto load_tile = [&](int buf, int kt) {
        const __half* ag = A + (size_t)(m0 + lr) * 512 + kt * 32 + lc;
        const __half* bg = W + (size_t)(n0 + lr) * 512 + kt * 32 + lc;
        __half* as = &As[buf * 5120 + lr * 40 + lc];
        __half* bs = &Bs[buf * 5120 + lr * 40 + lc];
        cpa16(as,     ag);
        cpa16(as + 8, ag + 8);
        cpa16(bs,     bg);
        cpa16(bs + 8, bg + 8);
        cp_commit();
    };
    const uint32_t a_loff =
        ((uint32_t)((lane & 7) + ((lane >> 3) & 1) * 8) * 40 + (lane >> 4) * 8) * 2;
    const uint32_t b_loff =
        ((uint32_t)((lane & 7) + ((lane >> 4) << 3)) * 40 + ((lane >> 3) & 1) * 8) * 2;

    load_tile(0, 0); load_tile(1, 1); load_tile(2, 2);
    for (int kt = 0; kt < 16; kt++) {
        cp_wait<2>();           // tile kt complete (<=2 newer groups pending)
        __syncthreads();        // visibility + prior-iter compute done
        if (kt + 3 < 16) load_tile((kt + 3) & 3, kt + 3);
        const uint32_t abase = shb + (uint32_t)((kt & 3) * 5120) * 2 + a_loff;
        const uint32_t bbase = shb + (uint32_t)(4 * 5120 + (kt & 3) * 5120) * 2 + b_loff;
#pragma unroll
        for (int ks = 0; ks < 2; ks++) {
            uint32_t af[2][4], bf[4][4];
#pragma unroll
            for (int mi = 0; mi < 2; mi++)
                ldsm_x4(af[mi], abase + (uint32_t)((wm * 32 + mi * 16) * 40 + ks * 16) * 2);
#pragma unroll
            for (int jn = 0; jn < 4; jn++)
                ldsm_x4(bf[jn], bbase + (uint32_t)((wn * 64 + jn * 16) * 40 + ks * 16) * 2);
#pragma unroll
            for (int mi = 0; mi < 2; mi++)
#pragma unroll
                for (int jn = 0; jn < 4; jn++) {
                    mma_f16(acc[mi][2 * jn],     af[mi], &bf[jn][0]);
                    mma_f16(acc[mi][2 * jn + 1], af[mi], &bf[jn][2]);
                }
        }
    }

    // vectorized epilogue: pair (e, e|1) -> one 2-element store
#pragma unroll
    for (int i = 0; i < 2; i++)
#pragma unroll
        for (int j = 0; j < 8; j++) {
            int col = n0 + wn * 64 + j * 8 + (lane & 3) * 2;
            float2 bb = __ldg((const float2*)&bias[col]);
#pragma unroll
            for (int half_ = 0; half_ < 2; half_++) {   // half_=0 -> row, 1 -> row+8
                int row = m0 + wm * 32 + i * 16 + (lane >> 2) + half_ * 8;
                float v0 = acc[i][j][half_ * 2]     + bb.x;
                float v1 = acc[i][j][half_ * 2 + 1] + bb.y;
                if (PERM) {
                    int bbx = row >> 11, l = row & (NL - 1);
                    size_t idx = (((size_t)(bbx * NH + (col >> 6))) * NL + l) * HD + (col & 63);
                    *(uint32_t*)&out[idx] = packh2(v0, v1);
                } else {
                    *(float2*)&out[(size_t)row * ND + col] = make_float2(v0, v1);
                }
            }
        }
}

__global__ __launch_bounds__(256, 2) void gemm16_qkv(
    const __half* __restrict__ xh, const __half* __restrict__ wh,
    const float* __restrict__ bq, const float* __restrict__ bk,
    const float* __restrict__ bv,
    __half* __restrict__ q, __half* __restrict__ k, __half* __restrict__ v)
{
    const size_t XN = (size_t)NB * NL * ND;
    const size_t WN = (size_t)ND * ND;
    int z = blockIdx.z;
    const __half* A = xh + (size_t)z * XN;
    const __half* W = wh + (size_t)z * WN;
    const float* bias = (z == 0) ? bq : (z == 1) ? bk : bv;
    __half* out = (z == 0) ? q : (z == 1) ? k : v;
    gemm16_body<1, __half>(A, W, bias, out, blockIdx.x * 128, blockIdx.y * 128);
}

__global__ __launch_bounds__(256, 2) void gemm16_o(
    const __half* __restrict__ A, const __half* __restrict__ W,
    const float* __restrict__ bias, float* __restrict__ out)
{
    gemm16_body<0, float>(A, W, bias, out, blockIdx.x * 128, blockIdx.y * 128);
}

// ============================================================================
// Fused attention (exact R12 best-known version): 128 q-rows/CTA, 8 warps,
// each warp = 16 q-rows x full 64-key chunk.
//   Sweep 1: QK^T -> exp(s/8 + bias) -> row sums l
//   Sweep 2: recompute QK^T -> p = exp*il -> attn write + P.V -> ctx (fp16)
// smem: Qs[128][72] + Ks[2][64][72] + Vs[2][64][72] + invl/lpart = 56,320 B
// ============================================================================
__global__ __launch_bounds__(256, 2) void attn_fused(
    const __half* __restrict__ Q, const __half* __restrict__ K,
    const __half* __restrict__ V, const __half* __restrict__ mbias,
    float* __restrict__ attn, __half* __restrict__ ctx)
{
    extern __shared__ __align__(16) __half sh[];
    __half* Qs = sh;                         // 128*72
    __half* Ks = sh + 9216;                  // 2 * 64*72
    __half* Vs = sh + 18432;                 // 2 * 64*72
    float* invl  = (float*)(sh + 27648);     // 128
    float* lpart = invl + 128;               // 128

    const int tid = threadIdx.x, lane = tid & 31, wid = tid >> 5;
    const int wq = wid;                      // 16 q-rows per warp
    const int bh = blockIdx.y, b = bh >> 3, h = bh & 7;
    const int q0 = blockIdx.x * 128;

    const __half* Qg = Q + ((size_t)bh * NL + q0) * HD;
    const __half* Kg = K + (size_t)bh * NL * HD;
    const __half* Vg = V + (size_t)bh * NL * HD;
    const __half* mbb = mbias + (size_t)b * NL * NL;

    const uint32_t shb = (uint32_t)__cvta_generic_to_shared(sh);
    const uint32_t k_loff =
        ((uint32_t)(((lane >> 4) << 3) + (lane & 7)) * 72 + (((lane >> 3) & 1) << 3)) * 2;
    const uint32_t v_loff =
        ((uint32_t)((((lane >> 3) & 1) << 3) + (lane & 7)) * 72 + ((lane >> 4) << 3)) * 2;

    const int ldr = tid >> 3, ldc = (tid & 7) * 8;

    auto loadQ = [&]() {
#pragma unroll
        for (int i = 0; i < 4; i++) {
            int r = ldr + 32 * i;
            cpa16(&Qs[r * 72 + ldc], Qg + (size_t)r * HD + ldc);
        }
    };
    auto loadK = [&](int buf, int ch) {
#pragma unroll
        for (int i = 0; i < 2; i++) {
            int r = ldr + 32 * i;
            cpa16(&Ks[buf * 4608 + r * 72 + ldc], Kg + (size_t)(ch * 64 + r) * HD + ldc);
        }
    };
    auto loadV = [&](int buf, int ch) {
#pragma unroll
        for (int i = 0; i < 2; i++) {
            int r = ldr + 32 * i;
            cpa16(&Vs[buf * 4608 + r * 72 + ldc], Vg + (size_t)(ch * 64 + r) * HD + ldc);
        }
    };

    const int rq  = wq * 16 + (lane >> 2);     // local q row (and +8)
    const int r0g = q0 + rq;                   // global q row
    const int kc  = (lane & 3) * 2;

    uint32_t qf[4][4];
    float lsum0 = 0.f, lsum1 = 0.f;

    // ---------------- sweep 1: row sums ----------------
    loadQ(); loadK(0, 0); cp_commit();
    for (int ch = 0; ch < 32; ch++) {
        if (ch < 31) { loadK((ch + 1) & 1, ch + 1); cp_commit(); cp_wait<1>(); }
        else         { cp_wait<0>(); }
        __syncthreads();
        if (ch == 0) {
#pragma unroll
            for (int s = 0; s < 4; s++) {
                int k0 = s * 16 + kc;
                qf[s][0] = *(const uint32_t*)&Qs[rq * 72 + k0];
                qf[s][1] = *(const uint32_t*)&Qs[(rq + 8) * 72 + k0];
                qf[s][2] = *(const uint32_t*)&Qs[rq * 72 + k0 + 8];
                qf[s][3] = *(const uint32_t*)&Qs[(rq + 8) * 72 + k0 + 8];
            }
        }
        const uint32_t ksb = shb + (uint32_t)(9216 + (ch & 1) * 4608) * 2 + k_loff;

        float acc[8][4];
#pragma unroll
        for (int j = 0; j < 8; j++)
#pragma unroll
            for (int e = 0; e < 4; e++) acc[j][e] = 0.f;
#pragma unroll
        for (int jp = 0; jp < 4; jp++)
#pragma unroll
            for (int s = 0; s < 4; s++) {
                uint32_t r[4];
                ldsm_x4(r, ksb + (uint32_t)(jp * 16 * 72 + s * 16) * 2);
                mma_f16(acc[2 * jp],     qf[s], &r[0]);
                mma_f16(acc[2 * jp + 1], qf[s], &r[2]);
            }
#pragma unroll
        for (int j = 0; j < 8; j++) {
            int colg = ch * 64 + j * 8 + kc;
            float2 m0 = __half22float2(*(const __half2*)&mbb[(size_t)r0g * NL + colg]);
            float2 m1 = __half22float2(*(const __half2*)&mbb[(size_t)(r0g + 8) * NL + colg]);
            lsum0 += __expf(fmaf(acc[j][0], 0.125f, m0.x))
                   + __expf(fmaf(acc[j][1], 0.125f, m0.y));
            lsum1 += __expf(fmaf(acc[j][2], 0.125f, m1.x))
                   + __expf(fmaf(acc[j][3], 0.125f, m1.y));
        }
        __syncthreads();
    }
    lsum0 += __shfl_xor_sync(0xffffffffu, lsum0, 1);
    lsum0 += __shfl_xor_sync(0xffffffffu, lsum0, 2);
    lsum1 += __shfl_xor_sync(0xffffffffu, lsum1, 1);
    lsum1 += __shfl_xor_sync(0xffffffffu, lsum1, 2);
    if ((lane & 3) == 0) {
        lpart[rq]     = lsum0;
        lpart[rq + 8] = lsum1;
    }
    __syncthreads();
    if (tid < 128) invl[tid] = 1.0f / lpart[tid];
    __syncthreads();

    const float il0 = invl[rq], il1 = invl[rq + 8];

    float oacc[8][4];
#pragma unroll
    for (int j = 0; j < 8; j++)
#pragma unroll
        for (int e = 0; e < 4; e++) oacc[j][e] = 0.f;

    // ---------------- sweep 2: attn write + P.V ----------------
    loadK(0, 0); loadV(0, 0); cp_commit();
    for (int ch = 0; ch < 32; ch++) {
        if (ch < 31) { loadK((ch + 1) & 1, ch + 1); loadV((ch + 1) & 1, ch + 1);
                       cp_commit(); cp_wait<1>(); }
        else         { cp_wait<0>(); }
        __syncthreads();
        const uint32_t ksb = shb + (uint32_t)(9216  + (ch & 1) * 4608) * 2 + k_loff;
        const uint32_t vsb = shb + (uint32_t)(18432 + (ch & 1) * 4608) * 2 + v_loff;

        float acc[8][4];
#pragma unroll
        for (int j = 0; j < 8; j++)
#pragma unroll
            for (int e = 0; e < 4; e++) acc[j][e] = 0.f;
#pragma unroll
        for (int jp = 0; jp < 4; jp++)
#pragma unroll
            for (int s = 0; s < 4; s++) {
                uint32_t r[4];
                ldsm_x4(r, ksb + (uint32_t)(jp * 16 * 72 + s * 16) * 2);
                mma_f16(acc[2 * jp],     qf[s], &r[0]);
                mma_f16(acc[2 * jp + 1], qf[s], &r[2]);
            }

        uint32_t pa[4][4];
#pragma unroll
        for (int j = 0; j < 8; j++) {
            int colg = ch * 64 + j * 8 + kc;
            float2 m0 = __half22float2(*(const __half2*)&mbb[(size_t)r0g * NL + colg]);
            float2 m1 = __half22float2(*(const __half2*)&mbb[(size_t)(r0g + 8) * NL + colg]);
            float p0 = __expf(fmaf(acc[j][0], 0.125f, m0.x)) * il0;
            float p1 = __expf(fmaf(acc[j][1], 0.125f, m0.y)) * il0;
            float p2 = __expf(fmaf(acc[j][2], 0.125f, m1.x)) * il1;
            float p3 = __expf(fmaf(acc[j][3], 0.125f, m1.y)) * il1;
            *(float2*)&attn[((size_t)bh * NL + r0g) * NL + colg]     = make_float2(p0, p1);
            *(float2*)&attn[((size_t)bh * NL + r0g + 8) * NL + colg] = make_float2(p2, p3);
            int s2 = j >> 1;
            if ((j & 1) == 0) { pa[s2][0] = packh2(p0, p1); pa[s2][1] = packh2(p2, p3); }
            else              { pa[s2][2] = packh2(p0, p1); pa[s2][3] = packh2(p2, p3); }
        }
#pragma unroll
        for (int s2 = 0; s2 < 4; s2++)
#pragma unroll
            for (int jnp = 0; jnp < 4; jnp++) {
                uint32_t r[4];
                ldsm_x4_t(r, vsb + (uint32_t)(s2 * 16 * 72 + jnp * 16) * 2);
                mma_f16(oacc[2 * jnp],     pa[s2], &r[0]);
                mma_f16(oacc[2 * jnp + 1], pa[s2], &r[2]);
            }
        __syncthreads();
    }

    // ---------------- ctx store (fp16), per-warp rows, smem staging ----------
    float* osum = (float*)Ks;   // 128 x 72 f32 = 36,864 B = Ks+Vs regions
#pragma unroll
    for (int jn = 0; jn < 8; jn++)
#pragma unroll
        for (int e = 0; e < 4; e++) {
            int row = wq * 16 + (lane >> 2) + (e >> 1) * 8;
            int col = jn * 8 + kc + (e & 1);
            osum[row * 72 + col] = oacc[jn][e];
        }
    __syncthreads();
    for (int i = tid; i < 128 * 16; i += 256) {
        int row = i >> 4, c4 = (i & 15) * 4;
        float4 v = *(const float4*)&osum[row * 72 + c4];
        uint2 o = make_uint2(packh2(v.x, v.y), packh2(v.z, v.w));
        *(uint2*)&ctx[((size_t)b * NL + q0 + row) * ND + h * HD + c4] = o;
    }
}

// ============================================================================
// launch
// ============================================================================
extern "C" void kernel_launch(void* const* d_in, const int* in_sizes, int n_in,
                              void* d_out, int out_size) {
    (void)in_sizes; (void)n_in;
    const float* xs[3] = { (const float*)d_in[0], (const float*)d_in[1], (const float*)d_in[2] };
    const int*   msk = (const int*)d_in[3];
    const float* Ws[4] = { (const float*)d_in[4], (const float*)d_in[6],
                           (const float*)d_in[8], (const float*)d_in[10] };
    const float* bq = (const float*)d_in[5];
    const float* bk = (const float*)d_in[7];
    const float* bv = (const float*)d_in[9];
    const float* bo = (const float*)d_in[11];

    const long long FINAL_N = (long long)NB * NL * ND;
    const long long ATTN_N  = (long long)NBH * NL * NL;

    float* outp = (float*)d_out;
    float *finalp, *attnp;
    if ((long long)out_size >= FINAL_N + ATTN_N) { finalp = outp; attnp = outp + FINAL_N; }
    else if ((long long)out_size == ATTN_N)      { attnp = outp;  finalp = g_final; }
    else                                         { finalp = outp; attnp = g_attn; }

    const int SM_G16  = 8 * 5120 * 2;                       // 81,920 B (4-stage)
    const int SM_ATTN = 27648 * 2 + 256 * 4;                // 56,320 B

    cudaFuncSetAttribute(gemm16_qkv, cudaFuncAttributeMaxDynamicSharedMemorySize, SM_G16);
    cudaFuncSetAttribute(gemm16_o,   cudaFuncAttributeMaxDynamicSharedMemorySize, SM_G16);
    cudaFuncSetAttribute(attn_fused, cudaFuncAttributeMaxDynamicSharedMemorySize, SM_ATTN);

    __half* qg;  cudaGetSymbolAddress((void**)&qg, g_qh);
    __half* kg;  cudaGetSymbolAddress((void**)&kg, g_kh);
    __half* vg;  cudaGetSymbolAddress((void**)&vg, g_vh);
    __half* xh;  cudaGetSymbolAddress((void**)&xh, g_xh);
    __half* wh;  cudaGetSymbolAddress((void**)&wh, g_wh);
    __half* mb;  cudaGetSymbolAddress((void**)&mb, g_mb);
    __half* cg;  cudaGetSymbolAddress((void**)&cg, g_ctxh);

    const size_t XN = (size_t)NB * NL * ND;      // 4,194,304  (XN/4 = 1<<20)
    const size_t WN = (size_t)ND * ND;           //   262,144  (WN/4 = 1<<16)
    const size_t MN = (size_t)NB * NL * NL;      // 16,777,216

    // conversions (fused launches)
    cvt_f16_x3<<<(int)(3 * (XN / 4) / 256), 256>>>(
        (const float4*)xs[0], (const float4*)xs[1], (const float4*)xs[2], (uint2*)xh);
    cvt_f16_w4<<<(int)(4 * (WN / 4) / 256), 256>>>(
        (const float4*)Ws[0], (const float4*)Ws[1], (const float4*)Ws[2], (const float4*)Ws[3],
        (uint2*)wh);
    cvt_maskbias<<<(int)(MN / 4 / 256), 256>>>((const int4*)msk, (uint2*)mb, (int)(MN / 4));

    // fused Q/K/V projections: one launch, grid.z selects the GEMM
    gemm16_qkv<<<dim3(64, 4, 3), 256, SM_G16>>>(xh, wh, bq, bk, bv, qg, kg, vg);

    // fused attention: 128 q-rows per CTA (best-known R12 version)
    attn_fused<<<dim3(NL / 128, NBH), 256, SM_ATTN>>>(qg, kg, vg, mb, attnp, cg);

    // output projection (fp16 inputs, fp32 out)
    gemm16_o<<<dim3(64, 4), 256, SM_G16>>>(cg, wh + 3 * WN, bo, finalp);
}